// round 2
// baseline (speedup 1.0000x reference)
#include <cuda_runtime.h>
#include <math.h>
#include <stdint.h>

#define B_  2
#define N_  1024
#define D_  1024
#define R_  16
#define H_  2048
#define T_  (B_*N_)
#define G3_ (3*D_)
#define DR_ (D_*R_)

// ---------------- scratch ----------------
__device__ float g_xp[(size_t)T_*G3_];
__device__ float g_hbuf[2][B_*D_];
__device__ float g_gruout[(size_t)T_*D_];
__device__ float g_beta[T_];
__device__ float g_gated[(size_t)T_*D_];
__device__ float g_hid[(size_t)T_*H_];
__device__ float g_V2[R_*H_];
__device__ float g_c2[R_];
__device__ float g_s[T_*R_];
__device__ int   g_cnt;
__device__ volatile int g_gen;

// ---------------- helpers ----------------
__device__ __forceinline__ void fma2(unsigned long long &d, unsigned long long a, unsigned long long b){
    asm("fma.rn.f32x2 %0, %1, %2, %0;" : "+l"(d) : "l"(a), "l"(b));
}
__device__ __forceinline__ unsigned long long dup2(float x){
    unsigned long long r; unsigned int xi = __float_as_uint(x);
    asm("mov.b64 %0, {%1, %2};" : "=l"(r) : "r"(xi), "r"(xi));
    return r;
}
__device__ __forceinline__ float2 un2(unsigned long long v){
    unsigned int lo, hi;
    asm("mov.b64 {%0, %1}, %2;" : "=r"(lo), "=r"(hi) : "l"(v));
    return make_float2(__uint_as_float(lo), __uint_as_float(hi));
}
__device__ __forceinline__ float gelu_tanh(float x){
    float c = x + 0.044715f * x * x * x;
    return 0.5f * x * (1.0f + tanhf(0.7978845608028654f * c));
}
__device__ __forceinline__ float sigm(float x){ return 1.0f / (1.0f + expf(-x)); }

// ---------------- SGEMM NT: C[M,N] = A[M,K] @ Bw[N,K]^T ----------------
// EPI 1: C=acc+bias   EPI 2: C=gelu(acc+bias)
// EPI 3: fused decoder epilogue: out[t,d] = latent[t,d] + gated[t,d]*sum_r (acc+bias)[t,d*16+r]*g_s[t,r]
#define BM 128
#define BN 128
#define BK 16
#define SPAD 4

template<int EPI>
__global__ __launch_bounds__(256) void sgemm_nt(
    const float* __restrict__ A, const float* __restrict__ Bw,
    const float* __restrict__ bias, float* __restrict__ C,
    int M, int N, int K,
    const float* __restrict__ latent, const float* __restrict__ gated)
{
    __shared__ float As[2][BK][BM + SPAD];
    __shared__ float Bs[2][BK][BN + SPAD];
    __shared__ float ss[(EPI==3) ? BM*16 : 1];

    const int tid = threadIdx.x;
    const int bn  = blockIdx.x, bm = blockIdx.y;
    const int tr  = tid >> 4, tc = tid & 15;

    const float* Ab = A  + (size_t)bm * BM * K;
    const float* Bb = Bw + (size_t)bn * BN * K;

    const int lr0 = tid >> 2;
    const int lc0 = (tid & 3) * 4;

    if (EPI == 3){
        for (int k = tid; k < BM*16; k += 256)
            ss[k] = g_s[(bm*BM + (k >> 4))*R_ + (k & 15)];
    }

    unsigned long long acc[8][4];
    #pragma unroll
    for (int i = 0; i < 8; i++)
        #pragma unroll
        for (int j = 0; j < 4; j++) acc[i][j] = 0ull;

    const int KT = K / BK;

    float4 ta0 = *(const float4*)&Ab[(size_t)lr0      * K + lc0];
    float4 ta1 = *(const float4*)&Ab[(size_t)(lr0+64) * K + lc0];
    float4 tb0 = *(const float4*)&Bb[(size_t)lr0      * K + lc0];
    float4 tb1 = *(const float4*)&Bb[(size_t)(lr0+64) * K + lc0];
    As[0][lc0+0][lr0]=ta0.x; As[0][lc0+1][lr0]=ta0.y; As[0][lc0+2][lr0]=ta0.z; As[0][lc0+3][lr0]=ta0.w;
    As[0][lc0+0][lr0+64]=ta1.x; As[0][lc0+1][lr0+64]=ta1.y; As[0][lc0+2][lr0+64]=ta1.z; As[0][lc0+3][lr0+64]=ta1.w;
    Bs[0][lc0+0][lr0]=tb0.x; Bs[0][lc0+1][lr0]=tb0.y; Bs[0][lc0+2][lr0]=tb0.z; Bs[0][lc0+3][lr0]=tb0.w;
    Bs[0][lc0+0][lr0+64]=tb1.x; Bs[0][lc0+1][lr0+64]=tb1.y; Bs[0][lc0+2][lr0+64]=tb1.z; Bs[0][lc0+3][lr0+64]=tb1.w;
    __syncthreads();

    int buf = 0;
    for (int kt = 0; kt < KT; kt++){
        if (kt + 1 < KT){
            const float* An = Ab + (size_t)(kt+1) * BK;
            const float* Bn = Bb + (size_t)(kt+1) * BK;
            ta0 = *(const float4*)&An[(size_t)lr0      * K + lc0];
            ta1 = *(const float4*)&An[(size_t)(lr0+64) * K + lc0];
            tb0 = *(const float4*)&Bn[(size_t)lr0      * K + lc0];
            tb1 = *(const float4*)&Bn[(size_t)(lr0+64) * K + lc0];
        }
        #pragma unroll
        for (int k = 0; k < BK; k++){
            float4 av0 = *(float4*)&As[buf][k][tr*8];
            float4 av1 = *(float4*)&As[buf][k][tr*8 + 4];
            ulonglong2 bv0 = *(ulonglong2*)&Bs[buf][k][tc*8];
            ulonglong2 bv1 = *(ulonglong2*)&Bs[buf][k][tc*8 + 4];
            unsigned long long ad[8];
            ad[0]=dup2(av0.x); ad[1]=dup2(av0.y); ad[2]=dup2(av0.z); ad[3]=dup2(av0.w);
            ad[4]=dup2(av1.x); ad[5]=dup2(av1.y); ad[6]=dup2(av1.z); ad[7]=dup2(av1.w);
            #pragma unroll
            for (int i = 0; i < 8; i++){
                fma2(acc[i][0], ad[i], bv0.x);
                fma2(acc[i][1], ad[i], bv0.y);
                fma2(acc[i][2], ad[i], bv1.x);
                fma2(acc[i][3], ad[i], bv1.y);
            }
        }
        if (kt + 1 < KT){
            buf ^= 1;
            As[buf][lc0+0][lr0]=ta0.x; As[buf][lc0+1][lr0]=ta0.y; As[buf][lc0+2][lr0]=ta0.z; As[buf][lc0+3][lr0]=ta0.w;
            As[buf][lc0+0][lr0+64]=ta1.x; As[buf][lc0+1][lr0+64]=ta1.y; As[buf][lc0+2][lr0+64]=ta1.z; As[buf][lc0+3][lr0+64]=ta1.w;
            Bs[buf][lc0+0][lr0]=tb0.x; Bs[buf][lc0+1][lr0]=tb0.y; Bs[buf][lc0+2][lr0]=tb0.z; Bs[buf][lc0+3][lr0]=tb0.w;
            Bs[buf][lc0+0][lr0+64]=tb1.x; Bs[buf][lc0+1][lr0+64]=tb1.y; Bs[buf][lc0+2][lr0+64]=tb1.z; Bs[buf][lc0+3][lr0+64]=tb1.w;
            __syncthreads();
        }
    }

    const int row0 = bm*BM + tr*8, col0 = bn*BN + tc*8;
    float bv[8];
    float4 q0 = *(const float4*)&bias[col0];
    float4 q1 = *(const float4*)&bias[col0 + 4];
    bv[0]=q0.x; bv[1]=q0.y; bv[2]=q0.z; bv[3]=q0.w;
    bv[4]=q1.x; bv[5]=q1.y; bv[6]=q1.z; bv[7]=q1.w;

    #pragma unroll
    for (int i = 0; i < 8; i++){
        float cv[8];
        #pragma unroll
        for (int j = 0; j < 4; j++){
            float2 p = un2(acc[i][j]);
            cv[2*j] = p.x + bv[2*j];
            cv[2*j+1] = p.y + bv[2*j+1];
        }
        if (EPI == 1){
            float4 o0 = make_float4(cv[0],cv[1],cv[2],cv[3]);
            float4 o1 = make_float4(cv[4],cv[5],cv[6],cv[7]);
            *(float4*)&C[(size_t)(row0+i)*N + col0]     = o0;
            *(float4*)&C[(size_t)(row0+i)*N + col0 + 4] = o1;
        } else if (EPI == 2){
            #pragma unroll
            for (int q = 0; q < 8; q++) cv[q] = gelu_tanh(cv[q]);
            float4 o0 = make_float4(cv[0],cv[1],cv[2],cv[3]);
            float4 o1 = make_float4(cv[4],cv[5],cv[6],cv[7]);
            *(float4*)&C[(size_t)(row0+i)*N + col0]     = o0;
            *(float4*)&C[(size_t)(row0+i)*N + col0 + 4] = o1;
        } else { // EPI == 3
            int r0 = (tc & 1) * 8;
            const float* srow = &ss[(tr*8 + i)*16 + r0];
            float p = 0.0f;
            #pragma unroll
            for (int j = 0; j < 8; j++) p += cv[j] * srow[j];
            p += __shfl_xor_sync(0xffffffffu, p, 1);
            if ((tc & 1) == 0){
                int d = bn*8 + (tc >> 1);
                size_t idx = (size_t)(row0 + i) * D_ + d;
                C[idx] = latent[idx] + gated[idx] * p;
            }
        }
    }
}

// ---------------- persistent GRU ----------------
#define GCTAS 128
__device__ __forceinline__ void grid_barrier(){
    __threadfence();
    __syncthreads();
    if (threadIdx.x == 0){
        int g = g_gen;
        if (atomicAdd(&g_cnt, 1) == GCTAS - 1){
            g_cnt = 0;
            __threadfence();
            g_gen = g + 1;
        } else {
            while (g_gen == g) { }
            __threadfence();
        }
    }
    __syncthreads();
}

__global__ void gru_kernel(const float* __restrict__ w_hh, const float* __restrict__ b_hh)
{
    extern __shared__ float sm[];
    float* w_s  = sm;             // 24 x 1024
    float* h_s  = sm + 24*D_;     // 2 x 1024
    float* hp_s = sm + 26*D_;     // 24 x 2

    const int tid = threadIdx.x, lane = tid & 31, warp = tid >> 5;
    const int d0 = blockIdx.x * 8;

    for (int l = warp; l < 24; l += 8){
        int grow = (l >> 3) * D_ + d0 + (l & 7);
        for (int k = lane*4; k < D_; k += 128)
            *(float4*)&w_s[l*D_ + k] = *(const float4*)&w_hh[(size_t)grow * D_ + k];
    }
    float bh[3];
    #pragma unroll
    for (int q = 0; q < 3; q++){
        int l = warp*3 + q;
        bh[q] = b_hh[(l >> 3) * D_ + d0 + (l & 7)];
    }
    __syncthreads();

    int pbuf = 0;
    for (int t = 0; t < N_; t++){
        if (t > 0){
            for (int k = tid*4; k < 2*D_; k += 1024)
                *(float4*)&h_s[k] = *(const float4*)&g_hbuf[pbuf][k];
        }
        __syncthreads();

        if (t > 0){
            ulonglong2 hv0[8], hv1[8];
            #pragma unroll
            for (int j = 0; j < 8; j++){
                hv0[j] = *(ulonglong2*)&h_s[lane*4 + j*128];
                hv1[j] = *(ulonglong2*)&h_s[D_ + lane*4 + j*128];
            }
            #pragma unroll
            for (int q = 0; q < 3; q++){
                int l = warp*3 + q;
                unsigned long long a0 = 0ull, a1 = 0ull;
                #pragma unroll
                for (int j = 0; j < 8; j++){
                    ulonglong2 wv = *(ulonglong2*)&w_s[l*D_ + lane*4 + j*128];
                    fma2(a0, wv.x, hv0[j].x); fma2(a0, wv.y, hv0[j].y);
                    fma2(a1, wv.x, hv1[j].x); fma2(a1, wv.y, hv1[j].y);
                }
                float2 p0 = un2(a0), p1 = un2(a1);
                float s0 = p0.x + p0.y, s1 = p1.x + p1.y;
                #pragma unroll
                for (int o = 16; o > 0; o >>= 1){
                    s0 += __shfl_xor_sync(0xffffffffu, s0, o);
                    s1 += __shfl_xor_sync(0xffffffffu, s1, o);
                }
                if (lane == 0){
                    hp_s[l*2 + 0] = s0 + bh[q];
                    hp_s[l*2 + 1] = s1 + bh[q];
                }
            }
        } else {
            if (lane == 0){
                #pragma unroll
                for (int q = 0; q < 3; q++){
                    int l = warp*3 + q;
                    hp_s[l*2 + 0] = bh[q];
                    hp_s[l*2 + 1] = bh[q];
                }
            }
        }
        __syncthreads();

        if (tid < 16){
            int i = tid & 7, b = tid >> 3;
            int d = d0 + i;
            size_t xb = ((size_t)(b*N_ + t)) * G3_ + d;
            float xr = g_xp[xb], xz = g_xp[xb + D_], xn = g_xp[xb + 2*D_];
            float hr = hp_s[i*2 + b];
            float hz = hp_s[(8 + i)*2 + b];
            float hn = hp_s[(16 + i)*2 + b];
            float r  = sigm(xr + hr);
            float z  = sigm(xz + hz);
            float ng = tanhf(xn + r*hn);
            float hprev = (t > 0) ? h_s[b*D_ + d] : 0.0f;
            float hnew  = (1.0f - z)*ng + z*hprev;
            g_hbuf[pbuf ^ 1][b*D_ + d] = hnew;
            g_gruout[((size_t)(b*N_ + t)) * D_ + d] = hnew;
        }
        pbuf ^= 1;
        grid_barrier();
    }
}

// ---------------- beta ----------------
__global__ void beta_kernel(const float* __restrict__ beta_w){
    int gw = (blockIdx.x * blockDim.x + threadIdx.x) >> 5;
    int lane = threadIdx.x & 31;
    if (gw >= T_) return;
    const float* h = &g_gruout[(size_t)gw * D_];
    float s = 0.0f;
    #pragma unroll
    for (int j = 0; j < 8; j++){
        float4 hv = *(const float4*)&h[lane*4 + j*128];
        float4 wv = *(const float4*)&beta_w[lane*4 + j*128];
        s += hv.x*wv.x + hv.y*wv.y + hv.z*wv.z + hv.w*wv.w;
    }
    #pragma unroll
    for (int o = 16; o > 0; o >>= 1) s += __shfl_xor_sync(0xffffffffu, s, o);
    if (lane == 0) g_beta[gw] = sigm(s);
}

// ---------------- gated scan ----------------
__global__ void gated_scan(const float* __restrict__ latent){
    int b = blockIdx.x >> 2;
    int d = (blockIdx.x & 3) * 256 + threadIdx.x;
    float g = 0.0f;
    size_t base = (size_t)b * N_ * D_ + d;
    const float* bet = &g_beta[b * N_];
    #pragma unroll 8
    for (int n = 0; n < N_; n++){
        float a = __ldg(&bet[n]);
        g = __ldg(&latent[base + (size_t)n * D_]) + a * g;
        g_gated[base + (size_t)n * D_] = g;
    }
}

// ---------------- V2, c2 ----------------
__global__ void v2_reduce(const float* __restrict__ w2){
    int r = blockIdx.y;
    int hcol = blockIdx.x * 256 + threadIdx.x;
    const float* p = w2 + ((size_t)DR_ + r) * H_ + hcol;
    float s = 0.0f;
    for (int d = 0; d < D_; d++) s += p[(size_t)d * R_ * H_];
    g_V2[r * H_ + hcol] = s;
}

__global__ void c2_kernel(const float* __restrict__ b2){
    int r = blockIdx.x;
    __shared__ float red[256];
    float s = 0.0f;
    for (int d = threadIdx.x; d < D_; d += 256) s += b2[DR_ + d*R_ + r];
    red[threadIdx.x] = s; __syncthreads();
    for (int o = 128; o > 0; o >>= 1){
        if (threadIdx.x < o) red[threadIdx.x] += red[threadIdx.x + o];
        __syncthreads();
    }
    if (threadIdx.x == 0) g_c2[r] = red[0];
}

// ---------------- s[t,r] ----------------
__global__ void s_kernel(){
    __shared__ float hs[H_];
    int t = blockIdx.x;
    int tid = threadIdx.x;   // 128
    for (int k = tid*4; k < H_; k += 512)
        *(float4*)&hs[k] = *(const float4*)&g_hid[(size_t)t * H_ + k];
    __syncthreads();
    int warp = tid >> 5, lane = tid & 31;
    #pragma unroll
    for (int rr = 0; rr < 4; rr++){
        int r = warp*4 + rr;
        const float* v = &g_V2[r * H_];
        float s = 0.0f;
        #pragma unroll
        for (int j = 0; j < 16; j++){
            float4 a = *(float4*)&hs[lane*4 + j*128];
            float4 w = *(const float4*)&v[lane*4 + j*128];
            s += a.x*w.x + a.y*w.y + a.z*w.z + a.w*w.w;
        }
        #pragma unroll
        for (int o = 16; o > 0; o >>= 1) s += __shfl_xor_sync(0xffffffffu, s, o);
        if (lane == 0) g_s[t*R_ + r] = s + g_c2[r];
    }
}

// ---------------- launch ----------------
extern "C" void kernel_launch(void* const* d_in, const int* in_sizes, int n_in,
                              void* d_out, int out_size)
{
    const float* latent = (const float*)d_in[0];
    const float* w_ih   = (const float*)d_in[1];
    const float* w_hh   = (const float*)d_in[2];
    const float* b_ih   = (const float*)d_in[3];
    const float* b_hh   = (const float*)d_in[4];
    const float* beta_w = (const float*)d_in[5];
    const float* dec_w1 = (const float*)d_in[6];
    const float* dec_b1 = (const float*)d_in[7];
    const float* dec_w2 = (const float*)d_in[8];
    const float* dec_b2 = (const float*)d_in[9];
    float* out = (float*)d_out;

    float* xp;   cudaGetSymbolAddress((void**)&xp, g_xp);
    float* hid;  cudaGetSymbolAddress((void**)&hid, g_hid);
    float* gated; cudaGetSymbolAddress((void**)&gated, g_gated);

    static int smem_set = 0;
    int gru_smem = (26*D_ + 48) * 4;
    if (!smem_set){
        cudaFuncSetAttribute(gru_kernel, cudaFuncAttributeMaxDynamicSharedMemorySize, gru_smem);
        smem_set = 1;
    }

    // xp = latent @ w_ih^T + b_ih
    sgemm_nt<1><<<dim3(G3_/BN, T_/BM), 256>>>(latent, w_ih, b_ih, xp, T_, G3_, D_, nullptr, nullptr);
    // GRU recurrence
    gru_kernel<<<GCTAS, 256, gru_smem>>>(w_hh, b_hh);
    // beta
    beta_kernel<<<T_*32/256, 256>>>(beta_w);
    // gated associative scan
    gated_scan<<<B_*4, 256>>>(latent);
    // hid = gelu(gated @ dec_w1^T + b1)
    sgemm_nt<2><<<dim3(H_/BN, T_/BM), 256>>>(gated, dec_w1, dec_b1, hid, T_, H_, D_, nullptr, nullptr);
    // V2, c2, s
    v2_reduce<<<dim3(H_/256, R_), 256>>>(dec_w2);
    c2_kernel<<<R_, 256>>>(dec_b2);
    s_kernel<<<T_, 128>>>();
    // fused decoder GEMM + control + residual
    sgemm_nt<3><<<dim3(DR_/BN, T_/BM), 256>>>(hid, dec_w2, dec_b2, out, T_, DR_, H_, latent, gated);
}